// round 11
// baseline (speedup 1.0000x reference)
#include <cuda_runtime.h>
#include <cuda_bf16.h>
#include <cstdint>

// Off-diagonal Gram sum via:
//   (1/D) sum_d [ (sum_b x2[b,d])^2 - sum_b x2[b,d]^2 ],  x2 = x*x.
//
// R11: 256-bit global loads (ld.global.v4.b64 -> LDG.E.256, Blackwell-only,
// never emitted by ptxas from C++). Each thread owns 8 consecutive floats
// (32B) of one chunk across 8 b-rows: 8 staged LDG.256 instead of 8 LDG.128
// at double width -> half the load instructions chip-wide at constant bytes.
// Loads land directly in u64 regs = native f32x2 operands. grid=147 x 512.

#define B_ROWS 32
#define THREADS 512
#define QROWS 8
#define D_CONST 150528
#define D8_CONST (D_CONST / 8)   // 18816

__device__ double g_acc = 0.0;
__device__ unsigned int g_count = 0;

typedef unsigned long long u64;

__device__ __forceinline__ void upk2(u64 v, float& lo, float& hi) {
    asm("mov.b64 {%0, %1}, %2;" : "=f"(lo), "=f"(hi) : "l"(v));
}
__device__ __forceinline__ u64 mul2(u64 a, u64 b) {
    u64 r; asm("mul.rn.f32x2 %0, %1, %2;" : "=l"(r) : "l"(a), "l"(b)); return r;
}
__device__ __forceinline__ u64 add2(u64 a, u64 b) {
    u64 r; asm("add.rn.f32x2 %0, %1, %2;" : "=l"(r) : "l"(a), "l"(b)); return r;
}
__device__ __forceinline__ u64 fma2(u64 a, u64 b, u64 c) {
    u64 r; asm("fma.rn.f32x2 %0, %1, %2, %3;" : "=l"(r) : "l"(a), "l"(b), "l"(c)); return r;
}

struct U256 { u64 a, b, c, d; };
__device__ __forceinline__ U256 ldg256(const float* p) {
    U256 r;
    asm volatile("ld.global.v4.b64 {%0, %1, %2, %3}, [%4];"
                 : "=l"(r.a), "=l"(r.b), "=l"(r.c), "=l"(r.d)
                 : "l"(p));
    return r;
}

__global__ void __launch_bounds__(THREADS, 2)
ortho_fixed_kernel(const float* __restrict__ in, float* __restrict__ out,
                   double inv_d, int nblocks) {
    const int tid  = threadIdx.x;
    const int lane = tid & 31;
    const int q    = lane >> 3;                       // b-quarter 0..3
    const int c    = lane & 7;                        // chunk slot within warp
    const int wid  = tid >> 5;
    const int gw   = blockIdx.x * (THREADS / 32) + wid;   // 147*16 = 2352 warps
    const int col8 = gw * 8 + c;                      // 2352*8 = 18816 = D8 exact

    // 8 staged 256-bit loads: rows q*8 .. q*8+7, 8 consecutive floats each.
    // Byte address = 4*(row*D + col8*8): row term mult of 32 (D%8==0),
    // col term = 32*col8 -> 32B aligned.
    const float* p = in + (size_t)(q * QROWS) * D_CONST + (size_t)col8 * 8;
    U256 v[QROWS];
    #pragma unroll
    for (int j = 0; j < QROWS; j++)
        v[j] = ldg256(p + (size_t)j * D_CONST);

    u64 s0 = 0ull, s1 = 0ull, s2 = 0ull, s3 = 0ull;
    u64 t0 = 0ull, t1 = 0ull, t2 = 0ull, t3 = 0ull;
    #pragma unroll
    for (int j = 0; j < QROWS; j++) {
        u64 a0 = mul2(v[j].a, v[j].a);
        u64 a1 = mul2(v[j].b, v[j].b);
        u64 a2 = mul2(v[j].c, v[j].c);
        u64 a3 = mul2(v[j].d, v[j].d);
        s0 = add2(s0, a0); t0 = fma2(a0, a0, t0);
        s1 = add2(s1, a1); t1 = fma2(a1, a1, t1);
        s2 = add2(s2, a2); t2 = fma2(a2, a2, t2);
        s3 = add2(s3, a3); t3 = fma2(a3, a3, t3);
    }

    // local x^4 sum (additive across quarters)
    float ta, tb, tsum = 0.f;
    upk2(t0, ta, tb); tsum += ta + tb;
    upk2(t1, ta, tb); tsum += ta + tb;
    upk2(t2, ta, tb); tsum += ta + tb;
    upk2(t3, ta, tb); tsum += ta + tb;

    // recombine s across the 4 b-quarters (lanes c, c+8, c+16, c+24);
    // 64-bit shfl on packed pairs (2x32-bit shfl each)
    s0 = add2(s0, __shfl_xor_sync(0xFFFFFFFFu, s0, 8));
    s0 = add2(s0, __shfl_xor_sync(0xFFFFFFFFu, s0, 16));
    s1 = add2(s1, __shfl_xor_sync(0xFFFFFFFFu, s1, 8));
    s1 = add2(s1, __shfl_xor_sync(0xFFFFFFFFu, s1, 16));
    s2 = add2(s2, __shfl_xor_sync(0xFFFFFFFFu, s2, 8));
    s2 = add2(s2, __shfl_xor_sync(0xFFFFFFFFu, s2, 16));
    s3 = add2(s3, __shfl_xor_sync(0xFFFFFFFFu, s3, 8));
    s3 = add2(s3, __shfl_xor_sync(0xFFFFFFFFu, s3, 16));

    float val = -tsum;
    if (q == 0) {
        float x, y, ss = 0.f;
        upk2(s0, x, y); ss += x * x + y * y;
        upk2(s1, x, y); ss += x * x + y * y;
        upk2(s2, x, y); ss += x * x + y * y;
        upk2(s3, x, y); ss += x * x + y * y;
        val += ss;
    }

    #pragma unroll
    for (int off = 16; off > 0; off >>= 1)
        val += __shfl_xor_sync(0xFFFFFFFFu, val, off);

    __shared__ float warp_sums[THREADS / 32];
    if (lane == 0) warp_sums[wid] = val;
    __syncthreads();

    if (wid == 0) {
        float blk = (lane < THREADS / 32) ? warp_sums[lane] : 0.f;
        #pragma unroll
        for (int off = 8; off > 0; off >>= 1)
            blk += __shfl_xor_sync(0xFFFFFFFFu, blk, off);
        if (lane == 0) {
            atomicAdd(&g_acc, (double)blk);
            __threadfence();
            unsigned int ticket = atomicAdd(&g_count, 1u);
            if (ticket == (unsigned int)nblocks - 1u) {
                out[0] = (float)(g_acc * inv_d);
                g_acc = 0.0;     // reset for next graph replay
                g_count = 0u;
            }
        }
    }
}

// Generic fallback (runtime shape), identical math.
__global__ void __launch_bounds__(256, 1)
ortho_generic_kernel(const float4* __restrict__ in, float* __restrict__ out,
                     int d4, double inv_d, int nblocks) {
    int idx = blockIdx.x * 256 + threadIdx.x;
    float s0 = 0.f, s1 = 0.f, s2 = 0.f, s3 = 0.f;
    float t0 = 0.f, t1 = 0.f, t2 = 0.f, t3 = 0.f;
    if (idx < d4) {
        #pragma unroll
        for (int b = 0; b < B_ROWS; b++) {
            float4 v = in[(size_t)b * d4 + idx];
            float a0 = v.x * v.x, a1 = v.y * v.y, a2 = v.z * v.z, a3 = v.w * v.w;
            s0 += a0; t0 = fmaf(a0, a0, t0);
            s1 += a1; t1 = fmaf(a1, a1, t1);
            s2 += a2; t2 = fmaf(a2, a2, t2);
            s3 += a3; t3 = fmaf(a3, a3, t3);
        }
    }
    float val = (fmaf(s0, s0, -t0) + fmaf(s1, s1, -t1))
              + (fmaf(s2, s2, -t2) + fmaf(s3, s3, -t3));
    #pragma unroll
    for (int off = 16; off > 0; off >>= 1)
        val += __shfl_xor_sync(0xFFFFFFFFu, val, off);
    __shared__ float ws[8];
    int lane = threadIdx.x & 31, wid = threadIdx.x >> 5;
    if (lane == 0) ws[wid] = val;
    __syncthreads();
    if (wid == 0) {
        float blk = (lane < 8) ? ws[lane] : 0.f;
        #pragma unroll
        for (int off = 4; off > 0; off >>= 1)
            blk += __shfl_xor_sync(0xFFFFFFFFu, blk, off);
        if (lane == 0) {
            atomicAdd(&g_acc, (double)blk);
            __threadfence();
            unsigned int ticket = atomicAdd(&g_count, 1u);
            if (ticket == (unsigned int)nblocks - 1u) {
                out[0] = (float)(g_acc * inv_d);
                g_acc = 0.0;
                g_count = 0u;
            }
        }
    }
}

extern "C" void kernel_launch(void* const* d_in, const int* in_sizes, int n_in,
                              void* d_out, int out_size) {
    int total = in_sizes[0];
    int D = total / B_ROWS;

    if (D == D_CONST) {
        int blocks = D8_CONST / ((THREADS / 32) * 8);   // 147, exact
        ortho_fixed_kernel<<<blocks, THREADS>>>((const float*)d_in[0], (float*)d_out,
                                                1.0 / (double)D, blocks);
    } else {
        int d4 = D / 4;
        int blocks = (d4 + 255) / 256;
        ortho_generic_kernel<<<blocks, 256>>>((const float4*)d_in[0], (float*)d_out,
                                              d4, 1.0 / (double)D, blocks);
    }
}